// round 1
// baseline (speedup 1.0000x reference)
#include <cuda_runtime.h>
#include <math.h>

#define BB 8
#define KK 2048
#define DD 1024
#define NN_INNER 2048
#define MROWS (BB * KK)   // 16384

// ---------------- scratch (device globals: no allocations allowed) ----------
__device__ float g_h[(size_t)MROWS * DD];          // RMSNorm output      64 MB
__device__ float g_u[(size_t)MROWS * NN_INNER];    // silu(u)            128 MB
__device__ float g_zs[(size_t)MROWS * NN_INNER];   // silu(z)            128 MB
__device__ float g_lam[(size_t)MROWS * NN_INNER];  // sigmoid gates      128 MB
__device__ float g_s[(size_t)MROWS * NN_INNER];    // scan out * gate    128 MB

// ---------------- RMSNorm ----------------------------------------------------
__global__ __launch_bounds__(256) void rmsnorm_kernel(
    const float* __restrict__ x, const float* __restrict__ w)
{
    int row = blockIdx.x;
    const float4* xr = (const float4*)(x + (size_t)row * DD);
    float4 v = xr[threadIdx.x];
    float ss = v.x * v.x + v.y * v.y + v.z * v.z + v.w * v.w;
    #pragma unroll
    for (int o = 16; o > 0; o >>= 1)
        ss += __shfl_xor_sync(0xffffffffu, ss, o);
    __shared__ float red[8];
    if ((threadIdx.x & 31) == 0) red[threadIdx.x >> 5] = ss;
    __syncthreads();
    float tot = red[0] + red[1] + red[2] + red[3] +
                red[4] + red[5] + red[6] + red[7];
    float inv = rsqrtf(tot * (1.0f / DD) + 1e-5f);
    float4 wv = ((const float4*)w)[threadIdx.x];
    float4 o;
    o.x = v.x * inv * wv.x;
    o.y = v.y * inv * wv.y;
    o.z = v.z * inv * wv.z;
    o.w = v.w * inv * wv.w;
    ((float4*)(g_h + (size_t)row * DD))[threadIdx.x] = o;
}

// ---------------- NT GEMM: C[M,N] = A[M,Kd] * B[N,Kd]^T ---------------------
// MODE 1: A=g_h,  B=W_in,  epilogue silu -> g_u (n<INNER) / g_zs (n>=INNER)
// MODE 2: A=g_u,  B=W_dt,  epilogue sigmoid(v + b_dt[n]) -> g_lam
// MODE 3: A=g_s,  B=W_out, epilogue x[m,n] + v -> out
template <int MODE>
__global__ __launch_bounds__(256) void gemm_nt(
    const float* __restrict__ Bm, int N, int Kd,
    const float* __restrict__ extra,   // MODE2: b_dt[N]; MODE3: x (flattened)
    float* __restrict__ outp)          // MODE3: d_out
{
    constexpr int BMt = 128, BNt = 128, BKt = 16, PAD = 4;
    __shared__ float As[BKt][BMt + PAD];
    __shared__ float Bs[BKt][BNt + PAD];

    const float* A;
    if (MODE == 1)      A = g_h;
    else if (MODE == 2) A = g_u;
    else                A = g_s;

    const int bm = blockIdx.y * BMt;
    const int bn = blockIdx.x * BNt;
    const int tid = threadIdx.x;
    const int lr = tid >> 2;            // 0..63
    const int lc = (tid & 3) << 2;      // 0,4,8,12
    const int tx = tid & 15;
    const int ty = tid >> 4;

    const float* Aptr0 = A  + (size_t)(bm + lr)      * Kd + lc;
    const float* Aptr1 = A  + (size_t)(bm + lr + 64) * Kd + lc;
    const float* Bptr0 = Bm + (size_t)(bn + lr)      * Kd + lc;
    const float* Bptr1 = Bm + (size_t)(bn + lr + 64) * Kd + lc;

    float acc[8][8];
    #pragma unroll
    for (int i = 0; i < 8; i++)
        #pragma unroll
        for (int j = 0; j < 8; j++) acc[i][j] = 0.0f;

    float4 pa0 = *(const float4*)Aptr0;
    float4 pa1 = *(const float4*)Aptr1;
    float4 pb0 = *(const float4*)Bptr0;
    float4 pb1 = *(const float4*)Bptr1;

    for (int kc = 0; kc < Kd; kc += BKt) {
        // stage current chunk into smem (transposed: [k][m])
        As[lc + 0][lr] = pa0.x; As[lc + 1][lr] = pa0.y;
        As[lc + 2][lr] = pa0.z; As[lc + 3][lr] = pa0.w;
        As[lc + 0][lr + 64] = pa1.x; As[lc + 1][lr + 64] = pa1.y;
        As[lc + 2][lr + 64] = pa1.z; As[lc + 3][lr + 64] = pa1.w;
        Bs[lc + 0][lr] = pb0.x; Bs[lc + 1][lr] = pb0.y;
        Bs[lc + 2][lr] = pb0.z; Bs[lc + 3][lr] = pb0.w;
        Bs[lc + 0][lr + 64] = pb1.x; Bs[lc + 1][lr + 64] = pb1.y;
        Bs[lc + 2][lr + 64] = pb1.z; Bs[lc + 3][lr + 64] = pb1.w;
        __syncthreads();

        // prefetch next chunk (overlaps with compute)
        if (kc + BKt < Kd) {
            pa0 = *(const float4*)(Aptr0 + kc + BKt);
            pa1 = *(const float4*)(Aptr1 + kc + BKt);
            pb0 = *(const float4*)(Bptr0 + kc + BKt);
            pb1 = *(const float4*)(Bptr1 + kc + BKt);
        }

        #pragma unroll
        for (int k = 0; k < BKt; k++) {
            float ra[8], rb[8];
            #pragma unroll
            for (int i = 0; i < 8; i++) ra[i] = As[k][ty * 8 + i];
            #pragma unroll
            for (int j = 0; j < 8; j++) rb[j] = Bs[k][tx * 8 + j];
            #pragma unroll
            for (int i = 0; i < 8; i++)
                #pragma unroll
                for (int j = 0; j < 8; j++)
                    acc[i][j] = fmaf(ra[i], rb[j], acc[i][j]);
        }
        __syncthreads();
    }

    // epilogue
    #pragma unroll
    for (int i = 0; i < 8; i++) {
        int m = bm + ty * 8 + i;
        #pragma unroll
        for (int j = 0; j < 8; j++) {
            int n = bn + tx * 8 + j;
            float v = acc[i][j];
            if (MODE == 1) {
                float sv = v / (1.0f + expf(-v));   // silu
                if (n < NN_INNER)
                    g_u[(size_t)m * NN_INNER + n] = sv;
                else
                    g_zs[(size_t)m * NN_INNER + (n - NN_INNER)] = sv;
            } else if (MODE == 2) {
                float t = v + extra[n];
                g_lam[(size_t)m * (size_t)N + n] = 1.0f / (1.0f + expf(-t));
            } else {
                outp[(size_t)m * (size_t)N + n] =
                    extra[(size_t)m * (size_t)N + n] + v;
            }
        }
    }
}

// ---------------- sequential scan over K, fused with silu(z) gate -----------
__global__ __launch_bounds__(256) void scan_kernel()
{
    int b = blockIdx.y;
    int j = blockIdx.x * 256 + threadIdx.x;
    size_t idx = (size_t)b * KK * NN_INNER + j;
    float s = 0.0f;
    float ln = g_lam[idx];
    float un = g_u[idx];
    float zn = g_zs[idx];
    for (int k = 0; k < KK; k++) {
        float l = ln, uu = un, zz = zn;
        if (k + 1 < KK) {           // one-ahead register prefetch
            ln = g_lam[idx + NN_INNER];
            un = g_u[idx + NN_INNER];
            zn = g_zs[idx + NN_INNER];
        }
        s = fmaf(l, s, (1.0f - l) * uu);
        g_s[idx] = s * zz;
        idx += NN_INNER;
    }
}

// ---------------- launch ------------------------------------------------------
extern "C" void kernel_launch(void* const* d_in, const int* in_sizes, int n_in,
                              void* d_out, int out_size)
{
    const float* x      = (const float*)d_in[0];
    const float* w_norm = (const float*)d_in[1];
    const float* W_in   = (const float*)d_in[2];
    const float* W_dt   = (const float*)d_in[3];
    const float* b_dt   = (const float*)d_in[4];
    const float* W_out  = (const float*)d_in[5];
    float* out = (float*)d_out;

    rmsnorm_kernel<<<MROWS, 256>>>(x, w_norm);

    gemm_nt<1><<<dim3(2 * NN_INNER / 128, MROWS / 128), 256>>>(
        W_in, 2 * NN_INNER, DD, nullptr, nullptr);

    gemm_nt<2><<<dim3(NN_INNER / 128, MROWS / 128), 256>>>(
        W_dt, NN_INNER, NN_INNER, b_dt, nullptr);

    scan_kernel<<<dim3(NN_INNER / 256, BB), 256>>>();

    gemm_nt<3><<<dim3(DD / 128, MROWS / 128), 256>>>(
        W_out, DD, NN_INNER, x, out);
}

// round 5
// speedup vs baseline: 1.6808x; 1.6808x over previous
#include <cuda_runtime.h>
#include <cuda_bf16.h>
#include <stdint.h>
#include <math.h>

#define BB 8
#define KK 2048
#define DD 1024
#define INNER 2048
#define MROWS (BB*KK)   // 16384

// ---------------- device scratch (no allocs allowed) ------------------------
__device__ __nv_bfloat16 g_hhi[(size_t)MROWS*DD];
__device__ __nv_bfloat16 g_hlo[(size_t)MROWS*DD];
__device__ __nv_bfloat16 g_uhi[(size_t)MROWS*INNER];
__device__ __nv_bfloat16 g_ulo[(size_t)MROWS*INNER];
__device__ float         g_zs [(size_t)MROWS*INNER];
__device__ float         g_lam[(size_t)MROWS*INNER];
__device__ __nv_bfloat16 g_shi[(size_t)MROWS*INNER];
__device__ __nv_bfloat16 g_slo[(size_t)MROWS*INNER];
__device__ __nv_bfloat16 g_wi_hi[(size_t)2*INNER*DD];
__device__ __nv_bfloat16 g_wi_lo[(size_t)2*INNER*DD];
__device__ __nv_bfloat16 g_wd_hi[(size_t)INNER*INNER];
__device__ __nv_bfloat16 g_wd_lo[(size_t)INNER*INNER];
__device__ __nv_bfloat16 g_wo_hi[(size_t)DD*INNER];
__device__ __nv_bfloat16 g_wo_lo[(size_t)DD*INNER];

// ---------------- PTX helpers ------------------------------------------------
__device__ __forceinline__ uint32_t smem_u32(const void* p) {
    uint32_t a;
    asm("{ .reg .u64 t; cvta.to.shared.u64 t, %1; cvt.u32.u64 %0, t; }"
        : "=r"(a) : "l"(p));
    return a;
}
__device__ __forceinline__ void cp_async16(uint32_t dst, const void* src) {
    asm volatile("cp.async.cg.shared.global [%0], [%1], 16;\n"
                 :: "r"(dst), "l"(src) : "memory");
}
__device__ __forceinline__ void cp_commit() {
    asm volatile("cp.async.commit_group;\n" ::: "memory");
}
template <int N>
__device__ __forceinline__ void cp_wait() {
    asm volatile("cp.async.wait_group %0;\n" :: "n"(N) : "memory");
}
__device__ __forceinline__ void ldsm4(uint32_t* r, uint32_t addr) {
    asm volatile("ldmatrix.sync.aligned.m8n8.x4.shared.b16 {%0,%1,%2,%3}, [%4];"
                 : "=r"(r[0]), "=r"(r[1]), "=r"(r[2]), "=r"(r[3]) : "r"(addr));
}
__device__ __forceinline__ void mma16816(float* c, const uint32_t* a,
                                         uint32_t b0, uint32_t b1) {
    asm volatile("mma.sync.aligned.m16n8k16.row.col.f32.bf16.bf16.f32 "
                 "{%0,%1,%2,%3}, {%4,%5,%6,%7}, {%8,%9}, {%0,%1,%2,%3};"
                 : "+f"(c[0]), "+f"(c[1]), "+f"(c[2]), "+f"(c[3])
                 : "r"(a[0]), "r"(a[1]), "r"(a[2]), "r"(a[3]), "r"(b0), "r"(b1));
}

// ---------------- weight fp32 -> bf16 hi/lo split ---------------------------
template <int W>
__global__ __launch_bounds__(256) void convert_w(const float* __restrict__ src)
{
    size_t n = (W == 0) ? (size_t)2*INNER*DD
             : (W == 1) ? (size_t)INNER*INNER : (size_t)DD*INNER;
    __nv_bfloat16* hi = (W == 0) ? g_wi_hi : (W == 1) ? g_wd_hi : g_wo_hi;
    __nv_bfloat16* lo = (W == 0) ? g_wi_lo : (W == 1) ? g_wd_lo : g_wo_lo;
    size_t n4 = n >> 2;
    const float4* s4 = (const float4*)src;
    for (size_t i = (size_t)blockIdx.x * blockDim.x + threadIdx.x; i < n4;
         i += (size_t)gridDim.x * blockDim.x) {
        float4 v = s4[i];
        __nv_bfloat16 h0 = __float2bfloat16(v.x), h1 = __float2bfloat16(v.y);
        __nv_bfloat16 h2 = __float2bfloat16(v.z), h3 = __float2bfloat16(v.w);
        __nv_bfloat162 hp0 = __halves2bfloat162(h0, h1);
        __nv_bfloat162 hp1 = __halves2bfloat162(h2, h3);
        __nv_bfloat162 lp0 = __halves2bfloat162(
            __float2bfloat16(v.x - __bfloat162float(h0)),
            __float2bfloat16(v.y - __bfloat162float(h1)));
        __nv_bfloat162 lp1 = __halves2bfloat162(
            __float2bfloat16(v.z - __bfloat162float(h2)),
            __float2bfloat16(v.w - __bfloat162float(h3)));
        *(uint2*)(hi + 4*i) = make_uint2(*(uint32_t*)&hp0, *(uint32_t*)&hp1);
        *(uint2*)(lo + 4*i) = make_uint2(*(uint32_t*)&lp0, *(uint32_t*)&lp1);
    }
}

// ---------------- RMSNorm -> bf16 hi/lo --------------------------------------
__global__ __launch_bounds__(256) void rmsnorm_kernel(
    const float* __restrict__ x, const float* __restrict__ w)
{
    int row = blockIdx.x;
    const float4* xr = (const float4*)(x + (size_t)row * DD);
    float4 v = xr[threadIdx.x];
    float ss = v.x*v.x + v.y*v.y + v.z*v.z + v.w*v.w;
    #pragma unroll
    for (int o = 16; o > 0; o >>= 1) ss += __shfl_xor_sync(0xffffffffu, ss, o);
    __shared__ float red[8];
    if ((threadIdx.x & 31) == 0) red[threadIdx.x >> 5] = ss;
    __syncthreads();
    float tot = red[0]+red[1]+red[2]+red[3]+red[4]+red[5]+red[6]+red[7];
    float inv = rsqrtf(tot * (1.0f / DD) + 1e-5f);
    float4 wv = ((const float4*)w)[threadIdx.x];
    float o0 = v.x*inv*wv.x, o1 = v.y*inv*wv.y, o2 = v.z*inv*wv.z, o3 = v.w*inv*wv.w;
    __nv_bfloat16 h0=__float2bfloat16(o0), h1=__float2bfloat16(o1);
    __nv_bfloat16 h2=__float2bfloat16(o2), h3=__float2bfloat16(o3);
    __nv_bfloat162 hp0 = __halves2bfloat162(h0,h1), hp1 = __halves2bfloat162(h2,h3);
    __nv_bfloat162 lp0 = __halves2bfloat162(
        __float2bfloat16(o0-__bfloat162float(h0)), __float2bfloat16(o1-__bfloat162float(h1)));
    __nv_bfloat162 lp1 = __halves2bfloat162(
        __float2bfloat16(o2-__bfloat162float(h2)), __float2bfloat16(o3-__bfloat162float(h3)));
    size_t base = (size_t)row * DD + threadIdx.x * 4;
    *(uint2*)(g_hhi + base) = make_uint2(*(uint32_t*)&hp0, *(uint32_t*)&hp1);
    *(uint2*)(g_hlo + base) = make_uint2(*(uint32_t*)&lp0, *(uint32_t*)&lp1);
}

// ---------------- mma.sync split-bf16 NT GEMM -------------------------------
// C[M,N] = A[M,Kd]*B[N,Kd]^T with A,B as bf16 hi/lo pairs; 3-term product.
// BM=BN=128, BK=32. 8 warps as 2(m) x 4(n): warp tile 64x32.
// smem rows padded to 80B for conflict-free ldmatrix. 4-stage cp.async.
#define ROWB     80
#define TEN_B    (128*ROWB)          // 10240 per tensor
#define STG_B    (4*TEN_B)           // 40960 per stage
#define NSTG     4
#define GEMM_SMEM (NSTG*STG_B)       // 163840

template <int MODE>
__global__ __launch_bounds__(256) void gemm_tc(
    const float* __restrict__ extra, float* __restrict__ outp)
{
    const __nv_bfloat16 *Ahi, *Alo, *Bhi, *Blo;
    int Kd;
    if (MODE == 1)      { Ahi=g_hhi; Alo=g_hlo; Bhi=g_wi_hi; Blo=g_wi_lo; Kd=DD; }
    else if (MODE == 2) { Ahi=g_uhi; Alo=g_ulo; Bhi=g_wd_hi; Blo=g_wd_lo; Kd=INNER; }
    else                { Ahi=g_shi; Alo=g_slo; Bhi=g_wo_hi; Blo=g_wo_lo; Kd=INNER; }
    const int NT = Kd / 32;

    extern __shared__ __align__(128) char sm[];
    uint32_t sbase = smem_u32(sm);
    const int tid = threadIdx.x;
    const int l   = tid & 31;
    const int wid = tid >> 5;
    const int bm  = blockIdx.y * 128;
    const int bn  = blockIdx.x * 128;
    const int warp_m = (wid & 1) * 64;
    const int warp_n = (wid >> 1) * 32;

    const __nv_bfloat16* srcA_hi = Ahi + (size_t)bm * Kd;
    const __nv_bfloat16* srcA_lo = Alo + (size_t)bm * Kd;
    const __nv_bfloat16* srcB_hi = Bhi + (size_t)bn * Kd;
    const __nv_bfloat16* srcB_lo = Blo + (size_t)bn * Kd;

    auto load_stage = [&](int stg, int kc) {
        const __nv_bfloat16* srcs[4] = {srcA_hi, srcA_lo, srcB_hi, srcB_lo};
        uint32_t base = sbase + stg * STG_B;
        #pragma unroll
        for (int i = 0; i < 8; i++) {
            int c   = tid + i * 256;
            int tns = c >> 9;
            int row = (c >> 2) & 127;
            int seg = c & 3;
            uint32_t dst = base + tns * TEN_B + row * ROWB + seg * 16;
            const char* src = (const char*)(srcs[tns] + (size_t)row * Kd + kc)
                              + seg * 16;
            cp_async16(dst, src);
        }
    };

    float acc[4][4][4];
    #pragma unroll
    for (int mi = 0; mi < 4; mi++)
        #pragma unroll
        for (int ni = 0; ni < 4; ni++)
            #pragma unroll
            for (int c = 0; c < 4; c++) acc[mi][ni][c] = 0.0f;

    // lane-constant ldmatrix row offsets
    const uint32_t a_off = (warp_m + (l & 15)) * ROWB + 16 * (l >> 4);
    const uint32_t b_off = (warp_n + (l & 15)) * ROWB + 16 * (l >> 4);

    // prologue: stages 0..2
    load_stage(0, 0);  cp_commit();
    load_stage(1, 32); cp_commit();
    load_stage(2, 64); cp_commit();

    for (int t = 0; t < NT; t++) {
        if (t == NT - 1)      cp_wait<0>();
        else if (t == NT - 2) cp_wait<1>();
        else                  cp_wait<2>();
        __syncthreads();
        if (t + 3 < NT) { load_stage((t + 3) & 3, (t + 3) * 32); cp_commit(); }

        uint32_t sb = sbase + (t & 3) * STG_B;
        #pragma unroll
        for (int k16 = 0; k16 < 2; k16++) {
            uint32_t koff = k16 * 32;
            uint32_t ah[4][4], al[4][4];
            #pragma unroll
            for (int mi = 0; mi < 4; mi++)
                ldsm4(ah[mi], sb + 0*TEN_B + a_off + mi * (16*ROWB) + koff);
            #pragma unroll
            for (int mi = 0; mi < 4; mi++)
                ldsm4(al[mi], sb + 1*TEN_B + a_off + mi * (16*ROWB) + koff);
            uint32_t bh[2][4], bl[2][4];
            #pragma unroll
            for (int g = 0; g < 2; g++) {
                ldsm4(bh[g], sb + 2*TEN_B + b_off + g * (16*ROWB) + koff);
                ldsm4(bl[g], sb + 3*TEN_B + b_off + g * (16*ROWB) + koff);
            }
            #pragma unroll
            for (int mi = 0; mi < 4; mi++)
                #pragma unroll
                for (int ni = 0; ni < 4; ni++) {
                    int g = ni >> 1, s = ni & 1;
                    mma16816(acc[mi][ni], ah[mi], bh[g][s], bh[g][s + 2]);
                    mma16816(acc[mi][ni], ah[mi], bl[g][s], bl[g][s + 2]);
                    mma16816(acc[mi][ni], al[mi], bh[g][s], bh[g][s + 2]);
                }
        }
    }

    // ---------------- epilogue from registers --------------------------------
    #pragma unroll
    for (int mi = 0; mi < 4; mi++) {
        int m0 = bm + warp_m + mi * 16 + (l >> 2);
        #pragma unroll
        for (int ni = 0; ni < 4; ni++) {
            int n0 = bn + warp_n + ni * 8 + 2 * (l & 3);
            #pragma unroll
            for (int half = 0; half < 2; half++) {
                int m = m0 + half * 8;
                float v0 = acc[mi][ni][half * 2 + 0];
                float v1 = acc[mi][ni][half * 2 + 1];
                if (MODE == 1) {
                    float s0 = v0 / (1.f + expf(-v0));
                    float s1 = v1 / (1.f + expf(-v1));
                    if (bn < INNER) {
                        __nv_bfloat16 h0 = __float2bfloat16(s0);
                        __nv_bfloat16 h1 = __float2bfloat16(s1);
                        __nv_bfloat162 hp = __halves2bfloat162(h0, h1);
                        __nv_bfloat162 lp = __halves2bfloat162(
                            __float2bfloat16(s0 - __bfloat162float(h0)),
                            __float2bfloat16(s1 - __bfloat162float(h1)));
                        size_t o = (size_t)m * INNER + n0;
                        *(uint32_t*)(g_uhi + o) = *(uint32_t*)&hp;
                        *(uint32_t*)(g_ulo + o) = *(uint32_t*)&lp;
                    } else {
                        size_t o = (size_t)m * INNER + (n0 - INNER);
                        *(float2*)(g_zs + o) = make_float2(s0, s1);
                    }
                } else if (MODE == 2) {
                    float2 bv = *(const float2*)(extra + n0);
                    float r0 = 1.f / (1.f + expf(-(v0 + bv.x)));
                    float r1 = 1.f / (1.f + expf(-(v1 + bv.y)));
                    *(float2*)(g_lam + (size_t)m * INNER + n0) = make_float2(r0, r1);
                } else {
                    size_t o = (size_t)m * DD + n0;
                    float2 xv = *(const float2*)(extra + o);
                    *(float2*)(outp + o) = make_float2(xv.x + v0, xv.y + v1);
                }
            }
        }
    }
}

// ---------------- sequential scan over K (depth-8 prefetch) -----------------
__global__ __launch_bounds__(128) void scan_kernel()
{
    const int PF = 8;
    int b = blockIdx.y;
    int j = blockIdx.x * 128 + threadIdx.x;
    size_t base = (size_t)b * KK * INNER + j;
    float lb[PF], ub[PF], zb[PF];
    #pragma unroll
    for (int p = 0; p < PF; p++) {
        size_t idx = base + (size_t)p * INNER;
        lb[p] = g_lam[idx];
        ub[p] = __bfloat162float(g_uhi[idx]) + __bfloat162float(g_ulo[idx]);
        zb[p] = g_zs[idx];
    }
    float s = 0.0f;
    size_t idx = base;
    #pragma unroll 8
    for (int k = 0; k < KK; k++) {
        int slot = k & (PF - 1);
        float lv = lb[slot], uu = ub[slot], zz = zb[slot];
        if (k + PF < KK) {
            size_t nidx = idx + (size_t)PF * INNER;
            lb[slot] = g_lam[nidx];
            ub[slot] = __bfloat162float(g_uhi[nidx]) + __bfloat162float(g_ulo[nidx]);
            zb[slot] = g_zs[nidx];
        }
        s = fmaf(lv, s, (1.0f - lv) * uu);
        float sg = s * zz;
        __nv_bfloat16 h = __float2bfloat16(sg);
        g_shi[idx] = h;
        g_slo[idx] = __float2bfloat16(sg - __bfloat162float(h));
        idx += INNER;
    }
}

// ---------------- launch ------------------------------------------------------
extern "C" void kernel_launch(void* const* d_in, const int* in_sizes, int n_in,
                              void* d_out, int out_size)
{
    const float* x      = (const float*)d_in[0];
    const float* w_norm = (const float*)d_in[1];
    const float* W_in   = (const float*)d_in[2];
    const float* W_dt   = (const float*)d_in[3];
    const float* b_dt   = (const float*)d_in[4];
    const float* W_out  = (const float*)d_in[5];
    float* out = (float*)d_out;

    cudaFuncSetAttribute(gemm_tc<1>, cudaFuncAttributeMaxDynamicSharedMemorySize, GEMM_SMEM);
    cudaFuncSetAttribute(gemm_tc<2>, cudaFuncAttributeMaxDynamicSharedMemorySize, GEMM_SMEM);
    cudaFuncSetAttribute(gemm_tc<3>, cudaFuncAttributeMaxDynamicSharedMemorySize, GEMM_SMEM);

    convert_w<0><<<512, 256>>>(W_in);
    convert_w<1><<<512, 256>>>(W_dt);
    convert_w<2><<<512, 256>>>(W_out);
    rmsnorm_kernel<<<MROWS, 256>>>(x, w_norm);

    gemm_tc<1><<<dim3(2*INNER/128, MROWS/128), 256, GEMM_SMEM>>>(nullptr, nullptr);
    gemm_tc<2><<<dim3(INNER/128,   MROWS/128), 256, GEMM_SMEM>>>(b_dt, nullptr);
    scan_kernel<<<dim3(INNER/128, BB), 128>>>();
    gemm_tc<3><<<dim3(DD/128,      MROWS/128), 256, GEMM_SMEM>>>(x, out);
}

// round 6
// speedup vs baseline: 2.9541x; 1.7576x over previous
#include <cuda_runtime.h>
#include <cuda_fp16.h>
#include <stdint.h>
#include <math.h>

#define BB 8
#define KK 2048
#define DD 1024
#define INNER 2048
#define MROWS (BB*KK)   // 16384

// ---------------- device scratch (no allocs allowed) ------------------------
__device__ __half g_h  [(size_t)MROWS*DD];      // RMSNorm out (fp16)    32 MB
__device__ __half g_u  [(size_t)MROWS*INNER];   // silu(u) fp16          64 MB
__device__ __half g_z  [(size_t)MROWS*INNER];   // silu(z) fp16          64 MB
__device__ float  g_lam[(size_t)MROWS*INNER];   // gates fp32           128 MB
__device__ __half g_s  [(size_t)MROWS*INNER];   // scan*gate fp16        64 MB
__device__ __half g_wi [(size_t)2*INNER*DD];    // W_in fp16             16 MB
__device__ __half g_wd [(size_t)INNER*INNER];   // W_dt fp16              8 MB
__device__ __half g_wo_hi[(size_t)DD*INNER];    // W_out hi               4 MB
__device__ __half g_wo_lo[(size_t)DD*INNER];    // W_out residual         4 MB

// ---------------- PTX helpers ------------------------------------------------
__device__ __forceinline__ uint32_t smem_u32(const void* p) {
    uint32_t a;
    asm("{ .reg .u64 t; cvta.to.shared.u64 t, %1; cvt.u32.u64 %0, t; }"
        : "=r"(a) : "l"(p));
    return a;
}
__device__ __forceinline__ void cp_async16(uint32_t dst, const void* src) {
    asm volatile("cp.async.cg.shared.global [%0], [%1], 16;\n"
                 :: "r"(dst), "l"(src) : "memory");
}
__device__ __forceinline__ void cp_commit() {
    asm volatile("cp.async.commit_group;\n" ::: "memory");
}
template <int N>
__device__ __forceinline__ void cp_wait() {
    asm volatile("cp.async.wait_group %0;\n" :: "n"(N) : "memory");
}
__device__ __forceinline__ void ldsm4(uint32_t* r, uint32_t addr) {
    asm volatile("ldmatrix.sync.aligned.m8n8.x4.shared.b16 {%0,%1,%2,%3}, [%4];"
                 : "=r"(r[0]), "=r"(r[1]), "=r"(r[2]), "=r"(r[3]) : "r"(addr));
}
__device__ __forceinline__ void mma16816(float* c, const uint32_t* a,
                                         uint32_t b0, uint32_t b1) {
    asm volatile("mma.sync.aligned.m16n8k16.row.col.f32.f16.f16.f32 "
                 "{%0,%1,%2,%3}, {%4,%5,%6,%7}, {%8,%9}, {%0,%1,%2,%3};"
                 : "+f"(c[0]), "+f"(c[1]), "+f"(c[2]), "+f"(c[3])
                 : "r"(a[0]), "r"(a[1]), "r"(a[2]), "r"(a[3]), "r"(b0), "r"(b1));
}
__device__ __forceinline__ uint32_t pack_half2(float a, float b) {
    __half2 h = __halves2half2(__float2half_rn(a), __float2half_rn(b));
    return *(uint32_t*)&h;
}

// ---------------- weight conversion ------------------------------------------
// W=0: W_in -> g_wi (fp16);  W=1: W_dt -> g_wd;  W=2: W_out -> hi + residual
template <int W>
__global__ __launch_bounds__(256) void convert_w(const float* __restrict__ src)
{
    size_t n = (W == 0) ? (size_t)2*INNER*DD
             : (W == 1) ? (size_t)INNER*INNER : (size_t)DD*INNER;
    size_t n4 = n >> 2;
    const float4* s4 = (const float4*)src;
    for (size_t i = (size_t)blockIdx.x * blockDim.x + threadIdx.x; i < n4;
         i += (size_t)gridDim.x * blockDim.x) {
        float4 v = s4[i];
        if (W == 2) {
            __half h0 = __float2half_rn(v.x), h1 = __float2half_rn(v.y);
            __half h2 = __float2half_rn(v.z), h3 = __float2half_rn(v.w);
            uint32_t hi0 = pack_half2(v.x, v.y), hi1 = pack_half2(v.z, v.w);
            uint32_t lo0 = pack_half2(v.x - __half2float(h0), v.y - __half2float(h1));
            uint32_t lo1 = pack_half2(v.z - __half2float(h2), v.w - __half2float(h3));
            *(uint2*)(g_wo_hi + 4*i) = make_uint2(hi0, hi1);
            *(uint2*)(g_wo_lo + 4*i) = make_uint2(lo0, lo1);
        } else {
            __half* dst = (W == 0) ? g_wi : g_wd;
            *(uint2*)(dst + 4*i) = make_uint2(pack_half2(v.x, v.y),
                                              pack_half2(v.z, v.w));
        }
    }
}

// ---------------- RMSNorm -> fp16 --------------------------------------------
__global__ __launch_bounds__(256) void rmsnorm_kernel(
    const float* __restrict__ x, const float* __restrict__ w)
{
    int row = blockIdx.x;
    const float4* xr = (const float4*)(x + (size_t)row * DD);
    float4 v = xr[threadIdx.x];
    float ss = v.x*v.x + v.y*v.y + v.z*v.z + v.w*v.w;
    #pragma unroll
    for (int o = 16; o > 0; o >>= 1) ss += __shfl_xor_sync(0xffffffffu, ss, o);
    __shared__ float red[8];
    if ((threadIdx.x & 31) == 0) red[threadIdx.x >> 5] = ss;
    __syncthreads();
    float tot = red[0]+red[1]+red[2]+red[3]+red[4]+red[5]+red[6]+red[7];
    float inv = rsqrtf(tot * (1.0f / DD) + 1e-5f);
    float4 wv = ((const float4*)w)[threadIdx.x];
    size_t base = (size_t)row * DD + threadIdx.x * 4;
    *(uint2*)(g_h + base) = make_uint2(
        pack_half2(v.x*inv*wv.x, v.y*inv*wv.y),
        pack_half2(v.z*inv*wv.z, v.w*inv*wv.w));
}

// ---------------- mma.sync fp16 NT GEMM --------------------------------------
// C[M,N] = A[M,Kd]*B[N,Kd]^T, fp32 accumulate.
// MODE 1: A=g_h, B=g_wi (1 term)  : epi silu -> g_u (n<INNER) / g_z
// MODE 2: A=g_u, B=g_wd (1 term)  : epi sigmoid(v+b_dt[n]) -> g_lam
// MODE 3: A=g_s, B=g_wo hi+lo (2 terms) : epi x + v -> out
// BM=BN=128, BK=32; 8 warps 2(m)x4(n), warp tile 64x32; 4-stage cp.async.
#define ROWB  80
#define TEN_B (128*ROWB)     // 10240 per tensor per stage
#define NSTG  4

template <int MODE>
__global__ __launch_bounds__(256) void gemm_tc(
    const float* __restrict__ extra, float* __restrict__ outp)
{
    constexpr int NTEN = (MODE == 3) ? 3 : 2;
    constexpr int STG_B = NTEN * TEN_B;
    const __half *A, *B0, *B1 = nullptr;
    int Kd;
    if (MODE == 1)      { A = g_h; B0 = g_wi;    Kd = DD;    }
    else if (MODE == 2) { A = g_u; B0 = g_wd;    Kd = INNER; }
    else                { A = g_s; B0 = g_wo_hi; B1 = g_wo_lo; Kd = INNER; }
    const int NT = Kd / 32;

    extern __shared__ __align__(128) char sm[];
    uint32_t sbase = smem_u32(sm);
    const int tid = threadIdx.x;
    const int l   = tid & 31;
    const int wid = tid >> 5;
    const int bm  = blockIdx.y * 128;
    const int bn  = blockIdx.x * 128;
    const int warp_m = (wid & 1) * 64;
    const int warp_n = (wid >> 1) * 32;

    const __half* srcs[NTEN];
    srcs[0] = A  + (size_t)bm * Kd;
    srcs[1] = B0 + (size_t)bn * Kd;
    if (MODE == 3) srcs[2] = B1 + (size_t)bn * Kd;

    auto load_stage = [&](int stg, int kc) {
        uint32_t base = sbase + stg * STG_B;
        #pragma unroll
        for (int i = 0; i < NTEN * 2; i++) {
            int c   = tid + i * 256;
            int tns = c >> 9;
            int row = (c >> 2) & 127;
            int seg = c & 3;
            uint32_t dst = base + tns * TEN_B + row * ROWB + seg * 16;
            const char* src = (const char*)(srcs[tns] + (size_t)row * Kd + kc)
                              + seg * 16;
            cp_async16(dst, src);
        }
    };

    float acc[4][4][4];
    #pragma unroll
    for (int mi = 0; mi < 4; mi++)
        #pragma unroll
        for (int ni = 0; ni < 4; ni++)
            #pragma unroll
            for (int c = 0; c < 4; c++) acc[mi][ni][c] = 0.0f;

    const uint32_t a_off = (warp_m + (l & 15)) * ROWB + 16 * (l >> 4);
    const uint32_t b_off = (warp_n + (l & 15)) * ROWB + 16 * (l >> 4);

    load_stage(0, 0);  cp_commit();
    load_stage(1, 32); cp_commit();
    load_stage(2, 64); cp_commit();

    for (int t = 0; t < NT; t++) {
        if (t == NT - 1)      cp_wait<0>();
        else if (t == NT - 2) cp_wait<1>();
        else                  cp_wait<2>();
        __syncthreads();
        if (t + 3 < NT) { load_stage((t + 3) & 3, (t + 3) * 32); cp_commit(); }

        uint32_t sb = sbase + (t & 3) * STG_B;
        #pragma unroll
        for (int k16 = 0; k16 < 2; k16++) {
            uint32_t koff = k16 * 32;
            uint32_t ah[4][4];
            #pragma unroll
            for (int mi = 0; mi < 4; mi++)
                ldsm4(ah[mi], sb + 0*TEN_B + a_off + mi * (16*ROWB) + koff);
            uint32_t bh[2][4];
            #pragma unroll
            for (int g = 0; g < 2; g++)
                ldsm4(bh[g], sb + 1*TEN_B + b_off + g * (16*ROWB) + koff);
            if (MODE == 3) {
                uint32_t bl[2][4];
                #pragma unroll
                for (int g = 0; g < 2; g++)
                    ldsm4(bl[g], sb + 2*TEN_B + b_off + g * (16*ROWB) + koff);
                #pragma unroll
                for (int mi = 0; mi < 4; mi++)
                    #pragma unroll
                    for (int ni = 0; ni < 4; ni++) {
                        int g = ni >> 1, s = ni & 1;
                        mma16816(acc[mi][ni], ah[mi], bh[g][s], bh[g][s + 2]);
                        mma16816(acc[mi][ni], ah[mi], bl[g][s], bl[g][s + 2]);
                    }
            } else {
                #pragma unroll
                for (int mi = 0; mi < 4; mi++)
                    #pragma unroll
                    for (int ni = 0; ni < 4; ni++) {
                        int g = ni >> 1, s = ni & 1;
                        mma16816(acc[mi][ni], ah[mi], bh[g][s], bh[g][s + 2]);
                    }
            }
        }
    }

    // ---------------- epilogue from registers --------------------------------
    #pragma unroll
    for (int mi = 0; mi < 4; mi++) {
        int m0 = bm + warp_m + mi * 16 + (l >> 2);
        #pragma unroll
        for (int ni = 0; ni < 4; ni++) {
            int n0 = bn + warp_n + ni * 8 + 2 * (l & 3);
            #pragma unroll
            for (int half = 0; half < 2; half++) {
                int m = m0 + half * 8;
                float v0 = acc[mi][ni][half * 2 + 0];
                float v1 = acc[mi][ni][half * 2 + 1];
                if (MODE == 1) {
                    float s0 = v0 / (1.f + expf(-v0));
                    float s1 = v1 / (1.f + expf(-v1));
                    if (bn < INNER) {
                        *(uint32_t*)(g_u + (size_t)m * INNER + n0) = pack_half2(s0, s1);
                    } else {
                        *(uint32_t*)(g_z + (size_t)m * INNER + (n0 - INNER)) =
                            pack_half2(s0, s1);
                    }
                } else if (MODE == 2) {
                    float2 bv = *(const float2*)(extra + n0);
                    float r0 = 1.f / (1.f + expf(-(v0 + bv.x)));
                    float r1 = 1.f / (1.f + expf(-(v1 + bv.y)));
                    *(float2*)(g_lam + (size_t)m * INNER + n0) = make_float2(r0, r1);
                } else {
                    size_t o = (size_t)m * DD + n0;
                    float2 xv = *(const float2*)(extra + o);
                    *(float2*)(outp + o) = make_float2(xv.x + v0, xv.y + v1);
                }
            }
        }
    }
}

// ---------------- sequential scan over K (depth-8 prefetch) -----------------
__global__ __launch_bounds__(128) void scan_kernel()
{
    const int PF = 8;
    int b = blockIdx.y;
    int j = blockIdx.x * 128 + threadIdx.x;
    size_t base = (size_t)b * KK * INNER + j;
    float lb[PF], ub[PF], zb[PF];
    #pragma unroll
    for (int p = 0; p < PF; p++) {
        size_t idx = base + (size_t)p * INNER;
        lb[p] = g_lam[idx];
        ub[p] = __half2float(g_u[idx]);
        zb[p] = __half2float(g_z[idx]);
    }
    float s = 0.0f;
    size_t idx = base;
    #pragma unroll 8
    for (int k = 0; k < KK; k++) {
        int slot = k & (PF - 1);
        float lv = lb[slot], uu = ub[slot], zz = zb[slot];
        if (k + PF < KK) {
            size_t nidx = idx + (size_t)PF * INNER;
            lb[slot] = g_lam[nidx];
            ub[slot] = __half2float(g_u[nidx]);
            zb[slot] = __half2float(g_z[nidx]);
        }
        s = fmaf(lv, s, (1.0f - lv) * uu);
        g_s[idx] = __float2half_rn(s * zz);
        idx += INNER;
    }
}

// ---------------- launch ------------------------------------------------------
extern "C" void kernel_launch(void* const* d_in, const int* in_sizes, int n_in,
                              void* d_out, int out_size)
{
    const float* x      = (const float*)d_in[0];
    const float* w_norm = (const float*)d_in[1];
    const float* W_in   = (const float*)d_in[2];
    const float* W_dt   = (const float*)d_in[3];
    const float* b_dt   = (const float*)d_in[4];
    const float* W_out  = (const float*)d_in[5];
    float* out = (float*)d_out;

    const int SM12 = NSTG * 2 * TEN_B;   //  81920
    const int SM3  = NSTG * 3 * TEN_B;   // 122880
    cudaFuncSetAttribute(gemm_tc<1>, cudaFuncAttributeMaxDynamicSharedMemorySize, SM12);
    cudaFuncSetAttribute(gemm_tc<2>, cudaFuncAttributeMaxDynamicSharedMemorySize, SM12);
    cudaFuncSetAttribute(gemm_tc<3>, cudaFuncAttributeMaxDynamicSharedMemorySize, SM3);

    convert_w<0><<<512, 256>>>(W_in);
    convert_w<1><<<512, 256>>>(W_dt);
    convert_w<2><<<512, 256>>>(W_out);
    rmsnorm_kernel<<<MROWS, 256>>>(x, w_norm);

    gemm_tc<1><<<dim3(2*INNER/128, MROWS/128), 256, SM12>>>(nullptr, nullptr);
    gemm_tc<2><<<dim3(INNER/128,   MROWS/128), 256, SM12>>>(b_dt, nullptr);
    scan_kernel<<<dim3(INNER/128, BB), 128>>>();
    gemm_tc<3><<<dim3(DD/128,      MROWS/128), 256, SM3>>>(x, out);
}

// round 8
// speedup vs baseline: 5.2191x; 1.7668x over previous
#include <cuda_runtime.h>
#include <cuda_fp16.h>
#include <stdint.h>
#include <math.h>

#define BB 8
#define KK 2048
#define DD 1024
#define INNER 2048
#define MROWS (BB*KK)   // 16384
#define SCHUNK 128      // scan chunk length
#define NCHUNK (KK/SCHUNK)  // 16

// ---------------- device scratch (no allocs allowed) ------------------------
__device__ __half g_h  [(size_t)MROWS*DD];      // RMSNorm out fp16      32 MB
__device__ __half g_u  [(size_t)MROWS*INNER];   // silu(u) fp16          64 MB
__device__ __half g_z  [(size_t)MROWS*INNER];   // silu(z) fp16          64 MB
__device__ __half g_lg [(size_t)MROWS*INNER];   // dt logit fp16         64 MB
__device__ __half g_s  [(size_t)MROWS*INNER];   // scan*gate fp16        64 MB
__device__ __half g_wi [(size_t)2*INNER*DD];    // W_in fp16             16 MB
__device__ __half g_wd [(size_t)INNER*INNER];   // W_dt fp16              8 MB
__device__ __half g_wo [(size_t)DD*INNER];      // W_out fp16             4 MB
__device__ float  g_P  [(size_t)BB*NCHUNK*INNER];  // chunk decay prod    1 MB
__device__ float  g_q  [(size_t)BB*NCHUNK*INNER];  // chunk partial       1 MB
__device__ float  g_S  [(size_t)BB*NCHUNK*INNER];  // chunk start state   1 MB

// ---------------- PTX helpers ------------------------------------------------
__device__ __forceinline__ uint32_t smem_u32(const void* p) {
    uint32_t a;
    asm("{ .reg .u64 t; cvta.to.shared.u64 t, %1; cvt.u32.u64 %0, t; }"
        : "=r"(a) : "l"(p));
    return a;
}
__device__ __forceinline__ void cp_async16(uint32_t dst, const void* src) {
    asm volatile("cp.async.cg.shared.global [%0], [%1], 16;\n"
                 :: "r"(dst), "l"(src) : "memory");
}
__device__ __forceinline__ void cp_commit() {
    asm volatile("cp.async.commit_group;\n" ::: "memory");
}
template <int N>
__device__ __forceinline__ void cp_wait() {
    asm volatile("cp.async.wait_group %0;\n" :: "n"(N) : "memory");
}
__device__ __forceinline__ void ldsm4(uint32_t* r, uint32_t addr) {
    asm volatile("ldmatrix.sync.aligned.m8n8.x4.shared.b16 {%0,%1,%2,%3}, [%4];"
                 : "=r"(r[0]), "=r"(r[1]), "=r"(r[2]), "=r"(r[3]) : "r"(addr));
}
__device__ __forceinline__ void mma16816(float* c, const uint32_t* a,
                                         uint32_t b0, uint32_t b1) {
    asm volatile("mma.sync.aligned.m16n8k16.row.col.f32.f16.f16.f32 "
                 "{%0,%1,%2,%3}, {%4,%5,%6,%7}, {%8,%9}, {%0,%1,%2,%3};"
                 : "+f"(c[0]), "+f"(c[1]), "+f"(c[2]), "+f"(c[3])
                 : "r"(a[0]), "r"(a[1]), "r"(a[2]), "r"(a[3]), "r"(b0), "r"(b1));
}
__device__ __forceinline__ uint32_t pack_half2(float a, float b) {
    __half2 h = __halves2half2(__float2half_rn(a), __float2half_rn(b));
    return *(uint32_t*)&h;
}

// ---------------- weight conversion fp32 -> fp16 -----------------------------
template <int W>
__global__ __launch_bounds__(256) void convert_w(const float* __restrict__ src)
{
    size_t n = (W == 0) ? (size_t)2*INNER*DD
             : (W == 1) ? (size_t)INNER*INNER : (size_t)DD*INNER;
    __half* dst = (W == 0) ? g_wi : (W == 1) ? g_wd : g_wo;
    size_t n4 = n >> 2;
    const float4* s4 = (const float4*)src;
    for (size_t i = (size_t)blockIdx.x * blockDim.x + threadIdx.x; i < n4;
         i += (size_t)gridDim.x * blockDim.x) {
        float4 v = s4[i];
        *(uint2*)(dst + 4*i) = make_uint2(pack_half2(v.x, v.y),
                                          pack_half2(v.z, v.w));
    }
}

// ---------------- RMSNorm -> fp16 --------------------------------------------
__global__ __launch_bounds__(256) void rmsnorm_kernel(
    const float* __restrict__ x, const float* __restrict__ w)
{
    int row = blockIdx.x;
    const float4* xr = (const float4*)(x + (size_t)row * DD);
    float4 v = xr[threadIdx.x];
    float ss = v.x*v.x + v.y*v.y + v.z*v.z + v.w*v.w;
    #pragma unroll
    for (int o = 16; o > 0; o >>= 1) ss += __shfl_xor_sync(0xffffffffu, ss, o);
    __shared__ float red[8];
    if ((threadIdx.x & 31) == 0) red[threadIdx.x >> 5] = ss;
    __syncthreads();
    float tot = red[0]+red[1]+red[2]+red[3]+red[4]+red[5]+red[6]+red[7];
    float inv = rsqrtf(tot * (1.0f / DD) + 1e-5f);
    float4 wv = ((const float4*)w)[threadIdx.x];
    size_t base = (size_t)row * DD + threadIdx.x * 4;
    *(uint2*)(g_h + base) = make_uint2(
        pack_half2(v.x*inv*wv.x, v.y*inv*wv.y),
        pack_half2(v.z*inv*wv.z, v.w*inv*wv.w));
}

// ---------------- mma.sync fp16 NT GEMM --------------------------------------
// C[M,N] = A[M,Kd]*B[N,Kd]^T, fp32 accumulate, 1 term.
// MODE 1: A=g_h, B=g_wi : epi silu -> g_u (n<INNER) / g_z
// MODE 2: A=g_u, B=g_wd : epi (v + b_dt[n]) -> g_lg fp16 logit
// MODE 3: A=g_s, B=g_wo : epi x + v -> out
// BM=BN=128, BK=32; 8 warps 2(m)x4(n), warp tile 64x32; 4-stage cp.async.
#define ROWB  80
#define TEN_B (128*ROWB)     // 10240 per tensor per stage
#define NSTG  4
#define STG_B (2*TEN_B)      // 20480
#define GEMM_SMEM (NSTG*STG_B)  // 81920 -> 2 CTAs/SM

template <int MODE>
__global__ __launch_bounds__(256, 2) void gemm_tc(
    const float* __restrict__ extra, float* __restrict__ outp)
{
    const __half *A, *B0;
    int Kd;
    if (MODE == 1)      { A = g_h; B0 = g_wi; Kd = DD;    }
    else if (MODE == 2) { A = g_u; B0 = g_wd; Kd = INNER; }
    else                { A = g_s; B0 = g_wo; Kd = INNER; }
    const int NT = Kd / 32;

    extern __shared__ __align__(128) char sm[];
    uint32_t sbase = smem_u32(sm);
    const int tid = threadIdx.x;
    const int l   = tid & 31;
    const int wid = tid >> 5;
    const int bm  = blockIdx.y * 128;
    const int bn  = blockIdx.x * 128;
    const int warp_m = (wid & 1) * 64;
    const int warp_n = (wid >> 1) * 32;

    const __half* srcA = A  + (size_t)bm * Kd;
    const __half* srcB = B0 + (size_t)bn * Kd;

    auto load_stage = [&](int stg, int kc) {
        uint32_t base = sbase + stg * STG_B;
        #pragma unroll
        for (int i = 0; i < 4; i++) {
            int c   = tid + i * 256;
            int tns = c >> 9;
            int row = (c >> 2) & 127;
            int seg = c & 3;
            uint32_t dst = base + tns * TEN_B + row * ROWB + seg * 16;
            const __half* sp = tns ? srcB : srcA;
            cp_async16(dst, (const char*)(sp + (size_t)row * Kd + kc) + seg * 16);
        }
    };

    float acc[4][4][4];
    #pragma unroll
    for (int mi = 0; mi < 4; mi++)
        #pragma unroll
        for (int ni = 0; ni < 4; ni++)
            #pragma unroll
            for (int c = 0; c < 4; c++) acc[mi][ni][c] = 0.0f;

    const uint32_t a_off = (warp_m + (l & 15)) * ROWB + 16 * (l >> 4);
    const uint32_t b_off = (warp_n + (l & 15)) * ROWB + 16 * (l >> 4);

    load_stage(0, 0);  cp_commit();
    load_stage(1, 32); cp_commit();
    load_stage(2, 64); cp_commit();

    for (int t = 0; t < NT; t++) {
        if (t == NT - 1)      cp_wait<0>();
        else if (t == NT - 2) cp_wait<1>();
        else                  cp_wait<2>();
        __syncthreads();
        if (t + 3 < NT) { load_stage((t + 3) & 3, (t + 3) * 32); cp_commit(); }

        uint32_t sb = sbase + (t & 3) * STG_B;
        #pragma unroll
        for (int k16 = 0; k16 < 2; k16++) {
            uint32_t koff = k16 * 32;
            uint32_t ah[4][4];
            #pragma unroll
            for (int mi = 0; mi < 4; mi++)
                ldsm4(ah[mi], sb + 0*TEN_B + a_off + mi * (16*ROWB) + koff);
            uint32_t bh[2][4];
            #pragma unroll
            for (int g = 0; g < 2; g++)
                ldsm4(bh[g], sb + 1*TEN_B + b_off + g * (16*ROWB) + koff);
            #pragma unroll
            for (int mi = 0; mi < 4; mi++)
                #pragma unroll
                for (int ni = 0; ni < 4; ni++) {
                    int g = ni >> 1, s = ni & 1;
                    mma16816(acc[mi][ni], ah[mi], bh[g][s], bh[g][s + 2]);
                }
        }
    }

    // ---------------- epilogue from registers --------------------------------
    #pragma unroll
    for (int mi = 0; mi < 4; mi++) {
        int m0 = bm + warp_m + mi * 16 + (l >> 2);
        #pragma unroll
        for (int ni = 0; ni < 4; ni++) {
            int n0 = bn + warp_n + ni * 8 + 2 * (l & 3);
            #pragma unroll
            for (int half = 0; half < 2; half++) {
                int m = m0 + half * 8;
                float v0 = acc[mi][ni][half * 2 + 0];
                float v1 = acc[mi][ni][half * 2 + 1];
                if (MODE == 1) {
                    float s0 = v0 / (1.f + expf(-v0));
                    float s1 = v1 / (1.f + expf(-v1));
                    if (bn < INNER)
                        *(uint32_t*)(g_u + (size_t)m * INNER + n0) = pack_half2(s0, s1);
                    else
                        *(uint32_t*)(g_z + (size_t)m * INNER + (n0 - INNER)) =
                            pack_half2(s0, s1);
                } else if (MODE == 2) {
                    float2 bv = *(const float2*)(extra + n0);
                    *(uint32_t*)(g_lg + (size_t)m * INNER + n0) =
                        pack_half2(v0 + bv.x, v1 + bv.y);
                } else {
                    size_t o = (size_t)m * DD + n0;
                    float2 xv = *(const float2*)(extra + o);
                    *(float2*)(outp + o) = make_float2(xv.x + v0, xv.y + v1);
                }
            }
        }
    }
}

// ---------------- chunked scan: pass 1 (per-chunk P, q) ---------------------
__global__ __launch_bounds__(256) void scan_pass1()
{
    int b = blockIdx.z, c = blockIdx.y;
    int j = blockIdx.x * 256 + threadIdx.x;
    size_t idx = ((size_t)b * KK + (size_t)c * SCHUNK) * INNER + j;
    float P = 1.0f, q = 0.0f;
    #pragma unroll 4
    for (int k = 0; k < SCHUNK; k++) {
        float lg = __half2float(g_lg[idx]);
        float u  = __half2float(g_u[idx]);
        float lam = 1.0f / (1.0f + expf(-lg));
        q = fmaf(lam, q, (1.0f - lam) * u);
        P *= lam;
        idx += INNER;
    }
    size_t o = ((size_t)b * NCHUNK + c) * INNER + j;
    g_P[o] = P;
    g_q[o] = q;
}

// ---------------- chunked scan: combine (serial over 16 chunks) -------------
__global__ __launch_bounds__(256) void scan_combine()
{
    int b = blockIdx.y;
    int j = blockIdx.x * 256 + threadIdx.x;
    float s = 0.0f;
    size_t o = (size_t)b * NCHUNK * INNER + j;
    #pragma unroll
    for (int c = 0; c < NCHUNK; c++) {
        g_S[o] = s;
        s = fmaf(g_P[o], s, g_q[o]);
        o += INNER;
    }
}

// ---------------- chunked scan: pass 2 (replay + gate) ----------------------
__global__ __launch_bounds__(256) void scan_pass2()
{
    int b = blockIdx.z, c = blockIdx.y;
    int j = blockIdx.x * 256 + threadIdx.x;
    float s = g_S[((size_t)b * NCHUNK + c) * INNER + j];
    size_t idx = ((size_t)b * KK + (size_t)c * SCHUNK) * INNER + j;
    #pragma unroll 4
    for (int k = 0; k < SCHUNK; k++) {
        float lg = __half2float(g_lg[idx]);
        float u  = __half2float(g_u[idx]);
        float zz = __half2float(g_z[idx]);
        float lam = 1.0f / (1.0f + expf(-lg));
        s = fmaf(lam, s, (1.0f - lam) * u);
        g_s[idx] = __float2half_rn(s * zz);
        idx += INNER;
    }
}

// ---------------- launch ------------------------------------------------------
extern "C" void kernel_launch(void* const* d_in, const int* in_sizes, int n_in,
                              void* d_out, int out_size)
{
    const float* x      = (const float*)d_in[0];
    const float* w_norm = (const float*)d_in[1];
    const float* W_in   = (const float*)d_in[2];
    const float* W_dt   = (const float*)d_in[3];
    const float* b_dt   = (const float*)d_in[4];
    const float* W_out  = (const float*)d_in[5];
    float* out = (float*)d_out;

    cudaFuncSetAttribute(gemm_tc<1>, cudaFuncAttributeMaxDynamicSharedMemorySize, GEMM_SMEM);
    cudaFuncSetAttribute(gemm_tc<2>, cudaFuncAttributeMaxDynamicSharedMemorySize, GEMM_SMEM);
    cudaFuncSetAttribute(gemm_tc<3>, cudaFuncAttributeMaxDynamicSharedMemorySize, GEMM_SMEM);

    convert_w<0><<<512, 256>>>(W_in);
    convert_w<1><<<512, 256>>>(W_dt);
    convert_w<2><<<512, 256>>>(W_out);
    rmsnorm_kernel<<<MROWS, 256>>>(x, w_norm);

    gemm_tc<1><<<dim3(2*INNER/128, MROWS/128), 256, GEMM_SMEM>>>(nullptr, nullptr);
    gemm_tc<2><<<dim3(INNER/128,   MROWS/128), 256, GEMM_SMEM>>>(b_dt, nullptr);

    scan_pass1 <<<dim3(INNER/256, NCHUNK, BB), 256>>>();
    scan_combine<<<dim3(INNER/256, BB),        256>>>();
    scan_pass2 <<<dim3(INNER/256, NCHUNK, BB), 256>>>();

    gemm_tc<3><<<dim3(DD/128,      MROWS/128), 256, GEMM_SMEM>>>(x, out);
}

// round 9
// speedup vs baseline: 5.7233x; 1.0966x over previous
#include <cuda_runtime.h>
#include <cuda_fp16.h>
#include <stdint.h>
#include <math.h>

#define BB 8
#define KK 2048
#define DD 1024
#define INNER 2048
#define MROWS (BB*KK)   // 16384
#define SCHUNK 128      // scan chunk length
#define NCHUNK (KK/SCHUNK)  // 16

// ---------------- device scratch (no allocs allowed) ------------------------
__device__ __half g_h  [(size_t)MROWS*DD];      // RMSNorm out fp16      32 MB
__device__ __half g_u  [(size_t)MROWS*INNER];   // silu(u) fp16          64 MB
__device__ __half g_z  [(size_t)MROWS*INNER];   // silu(z) fp16          64 MB
__device__ __half g_lg [(size_t)MROWS*INNER];   // dt logit fp16         64 MB
__device__ __half g_s  [(size_t)MROWS*INNER];   // scan*gate fp16        64 MB
__device__ __half g_wi [(size_t)2*INNER*DD];    // W_in fp16             16 MB
__device__ __half g_wd [(size_t)INNER*INNER];   // W_dt fp16              8 MB
__device__ __half g_wo [(size_t)DD*INNER];      // W_out fp16             4 MB
__device__ float  g_P  [(size_t)BB*NCHUNK*INNER];  // chunk decay prod    1 MB
__device__ float  g_q  [(size_t)BB*NCHUNK*INNER];  // chunk partial       1 MB
__device__ float  g_S  [(size_t)BB*NCHUNK*INNER];  // chunk start state   1 MB

// ---------------- PTX helpers ------------------------------------------------
__device__ __forceinline__ uint32_t smem_u32(const void* p) {
    uint32_t a;
    asm("{ .reg .u64 t; cvta.to.shared.u64 t, %1; cvt.u32.u64 %0, t; }"
        : "=r"(a) : "l"(p));
    return a;
}
__device__ __forceinline__ void cp_async16(uint32_t dst, const void* src) {
    asm volatile("cp.async.cg.shared.global [%0], [%1], 16;\n"
                 :: "r"(dst), "l"(src) : "memory");
}
__device__ __forceinline__ void cp_commit() {
    asm volatile("cp.async.commit_group;\n" ::: "memory");
}
template <int N>
__device__ __forceinline__ void cp_wait() {
    asm volatile("cp.async.wait_group %0;\n" :: "n"(N) : "memory");
}
__device__ __forceinline__ void ldsm4(uint32_t* r, uint32_t addr) {
    asm volatile("ldmatrix.sync.aligned.m8n8.x4.shared.b16 {%0,%1,%2,%3}, [%4];"
                 : "=r"(r[0]), "=r"(r[1]), "=r"(r[2]), "=r"(r[3]) : "r"(addr));
}
__device__ __forceinline__ void mma16816(float* c, const uint32_t* a,
                                         uint32_t b0, uint32_t b1) {
    asm volatile("mma.sync.aligned.m16n8k16.row.col.f32.f16.f16.f32 "
                 "{%0,%1,%2,%3}, {%4,%5,%6,%7}, {%8,%9}, {%0,%1,%2,%3};"
                 : "+f"(c[0]), "+f"(c[1]), "+f"(c[2]), "+f"(c[3])
                 : "r"(a[0]), "r"(a[1]), "r"(a[2]), "r"(a[3]), "r"(b0), "r"(b1));
}
__device__ __forceinline__ uint32_t pack_half2(float a, float b) {
    __half2 h = __halves2half2(__float2half_rn(a), __float2half_rn(b));
    return *(uint32_t*)&h;
}

// ---------------- fused weight conversion fp32 -> fp16 -----------------------
__global__ __launch_bounds__(256) void convert_all(
    const float* __restrict__ wi, const float* __restrict__ wd,
    const float* __restrict__ wo)
{
    const size_t n0 = (size_t)2*INNER*DD >> 2;
    const size_t n1 = (size_t)INNER*INNER >> 2;
    const size_t n2 = (size_t)DD*INNER   >> 2;
    size_t stride = (size_t)gridDim.x * blockDim.x;
    size_t t0 = (size_t)blockIdx.x * blockDim.x + threadIdx.x;
    for (size_t i = t0; i < n0; i += stride) {
        float4 v = ((const float4*)wi)[i];
        *(uint2*)(g_wi + 4*i) = make_uint2(pack_half2(v.x, v.y), pack_half2(v.z, v.w));
    }
    for (size_t i = t0; i < n1; i += stride) {
        float4 v = ((const float4*)wd)[i];
        *(uint2*)(g_wd + 4*i) = make_uint2(pack_half2(v.x, v.y), pack_half2(v.z, v.w));
    }
    for (size_t i = t0; i < n2; i += stride) {
        float4 v = ((const float4*)wo)[i];
        *(uint2*)(g_wo + 4*i) = make_uint2(pack_half2(v.x, v.y), pack_half2(v.z, v.w));
    }
}

// ---------------- RMSNorm -> fp16 --------------------------------------------
__global__ __launch_bounds__(256) void rmsnorm_kernel(
    const float* __restrict__ x, const float* __restrict__ w)
{
    int row = blockIdx.x;
    const float4* xr = (const float4*)(x + (size_t)row * DD);
    float4 v = xr[threadIdx.x];
    float ss = v.x*v.x + v.y*v.y + v.z*v.z + v.w*v.w;
    #pragma unroll
    for (int o = 16; o > 0; o >>= 1) ss += __shfl_xor_sync(0xffffffffu, ss, o);
    __shared__ float red[8];
    if ((threadIdx.x & 31) == 0) red[threadIdx.x >> 5] = ss;
    __syncthreads();
    float tot = red[0]+red[1]+red[2]+red[3]+red[4]+red[5]+red[6]+red[7];
    float inv = rsqrtf(tot * (1.0f / DD) + 1e-5f);
    float4 wv = ((const float4*)w)[threadIdx.x];
    size_t base = (size_t)row * DD + threadIdx.x * 4;
    *(uint2*)(g_h + base) = make_uint2(
        pack_half2(v.x*inv*wv.x, v.y*inv*wv.y),
        pack_half2(v.z*inv*wv.z, v.w*inv*wv.w));
}

// ---------------- mma.sync fp16 NT GEMM --------------------------------------
// C[M,N] = A[M,Kd]*B[N,Kd]^T, fp32 accumulate.
// MODE 1: A=g_h, B=g_wi : epi silu -> g_u (n<INNER) / g_z
// MODE 2: A=g_u, B=g_wd : epi (v + b_dt[n]) -> g_lg fp16 logit
// MODE 3: A=g_s, B=g_wo : epi x + v -> out
// BM=BN=128, BK=64; 8 warps 2(m)x4(n), warp tile 64x32; 3-stage cp.async.
// ROWB=144 (stride ≡ 16 mod 128 -> conflict-free ldmatrix rows).
#define ROWB  144
#define TEN_B (128*ROWB)        // 18432 per tensor per stage
#define NSTG  3
#define STG_B (2*TEN_B)         // 36864
#define GEMM_SMEM (NSTG*STG_B)  // 110592 -> 2 CTAs/SM

template <int MODE>
__global__ __launch_bounds__(256, 2) void gemm_tc(
    const float* __restrict__ extra, float* __restrict__ outp)
{
    const __half *A, *B0;
    int Kd;
    if (MODE == 1)      { A = g_h; B0 = g_wi; Kd = DD;    }
    else if (MODE == 2) { A = g_u; B0 = g_wd; Kd = INNER; }
    else                { A = g_s; B0 = g_wo; Kd = INNER; }
    const int NT = Kd / 64;

    extern __shared__ __align__(128) char sm[];
    uint32_t sbase = smem_u32(sm);
    const int tid = threadIdx.x;
    const int l   = tid & 31;
    const int wid = tid >> 5;
    const int bm  = blockIdx.y * 128;
    const int bn  = blockIdx.x * 128;
    const int warp_m = (wid & 1) * 64;
    const int warp_n = (wid >> 1) * 32;

    const __half* srcA = A  + (size_t)bm * Kd;
    const __half* srcB = B0 + (size_t)bn * Kd;

    auto load_stage = [&](int stg, int kc) {
        uint32_t base = sbase + stg * STG_B;
        #pragma unroll
        for (int i = 0; i < 8; i++) {
            int c   = tid + i * 256;          // 0..2047
            int tns = c >> 10;                // 0: A, 1: B
            int idx = c & 1023;
            int row = idx >> 3;               // 0..127
            int seg = idx & 7;                // 0..7 (16B each)
            uint32_t dst = base + tns * TEN_B + row * ROWB + seg * 16;
            const __half* sp = tns ? srcB : srcA;
            cp_async16(dst, (const char*)(sp + (size_t)row * Kd + kc) + seg * 16);
        }
    };

    float acc[4][4][4];
    #pragma unroll
    for (int mi = 0; mi < 4; mi++)
        #pragma unroll
        for (int ni = 0; ni < 4; ni++)
            #pragma unroll
            for (int c = 0; c < 4; c++) acc[mi][ni][c] = 0.0f;

    const uint32_t a_off = (warp_m + (l & 15)) * ROWB + 16 * (l >> 4);
    const uint32_t b_off = (warp_n + (l & 15)) * ROWB + 16 * (l >> 4);

    load_stage(0, 0);  cp_commit();
    load_stage(1, 64); cp_commit();

    for (int t = 0; t < NT; t++) {
        if (t + 1 < NT) cp_wait<1>();
        else            cp_wait<0>();
        __syncthreads();
        if (t + 2 < NT) {
            int s = t + 2; s -= (s >= 3) ? 3 : 0; s -= (s >= 3) ? 3 : 0;
            load_stage((t + 2) % 3, (t + 2) * 64);
            cp_commit();
        }

        int cs = t % 3;
        uint32_t sb = sbase + cs * STG_B;
        #pragma unroll
        for (int k16 = 0; k16 < 4; k16++) {
            uint32_t koff = k16 * 32;
            uint32_t ah[4][4];
            #pragma unroll
            for (int mi = 0; mi < 4; mi++)
                ldsm4(ah[mi], sb + 0*TEN_B + a_off + mi * (16*ROWB) + koff);
            uint32_t bh[2][4];
            #pragma unroll
            for (int g = 0; g < 2; g++)
                ldsm4(bh[g], sb + 1*TEN_B + b_off + g * (16*ROWB) + koff);
            #pragma unroll
            for (int mi = 0; mi < 4; mi++)
                #pragma unroll
                for (int ni = 0; ni < 4; ni++) {
                    int g = ni >> 1, s = ni & 1;
                    mma16816(acc[mi][ni], ah[mi], bh[g][s], bh[g][s + 2]);
                }
        }
    }

    // ---------------- epilogue from registers --------------------------------
    #pragma unroll
    for (int mi = 0; mi < 4; mi++) {
        int m0 = bm + warp_m + mi * 16 + (l >> 2);
        #pragma unroll
        for (int ni = 0; ni < 4; ni++) {
            int n0 = bn + warp_n + ni * 8 + 2 * (l & 3);
            #pragma unroll
            for (int half = 0; half < 2; half++) {
                int m = m0 + half * 8;
                float v0 = acc[mi][ni][half * 2 + 0];
                float v1 = acc[mi][ni][half * 2 + 1];
                if (MODE == 1) {
                    float s0 = v0 / (1.f + expf(-v0));
                    float s1 = v1 / (1.f + expf(-v1));
                    if (bn < INNER)
                        *(uint32_t*)(g_u + (size_t)m * INNER + n0) = pack_half2(s0, s1);
                    else
                        *(uint32_t*)(g_z + (size_t)m * INNER + (n0 - INNER)) =
                            pack_half2(s0, s1);
                } else if (MODE == 2) {
                    float2 bv = *(const float2*)(extra + n0);
                    *(uint32_t*)(g_lg + (size_t)m * INNER + n0) =
                        pack_half2(v0 + bv.x, v1 + bv.y);
                } else {
                    size_t o = (size_t)m * DD + n0;
                    float2 xv = *(const float2*)(extra + o);
                    *(float2*)(outp + o) = make_float2(xv.x + v0, xv.y + v1);
                }
            }
        }
    }
}

// ---------------- chunked scan (half2-vectorized, 2 channels/thread) --------
__global__ __launch_bounds__(256) void scan_pass1()
{
    int b = blockIdx.z, c = blockIdx.y;
    int j = blockIdx.x * 256 + threadIdx.x;          // channel-pair 0..1023
    const int I2 = INNER / 2;
    size_t idx = ((size_t)b * KK + (size_t)c * SCHUNK) * I2 + j;
    const __half2* lg2 = (const __half2*)g_lg;
    const __half2* u2  = (const __half2*)g_u;
    float2 P = make_float2(1.f, 1.f), q = make_float2(0.f, 0.f);
    #pragma unroll 4
    for (int k = 0; k < SCHUNK; k++) {
        float2 lg = __half22float2(lg2[idx]);
        float2 u  = __half22float2(u2[idx]);
        float la = 1.f / (1.f + expf(-lg.x));
        float lb = 1.f / (1.f + expf(-lg.y));
        q.x = fmaf(la, q.x, (1.f - la) * u.x);
        q.y = fmaf(lb, q.y, (1.f - lb) * u.y);
        P.x *= la; P.y *= lb;
        idx += I2;
    }
    size_t o = ((size_t)b * NCHUNK + c) * I2 + j;
    ((float2*)g_P)[o] = P;
    ((float2*)g_q)[o] = q;
}

__global__ __launch_bounds__(256) void scan_combine()
{
    int b = blockIdx.y;
    int j = blockIdx.x * 256 + threadIdx.x;          // channel-pair 0..1023
    const int I2 = INNER / 2;
    float2 s = make_float2(0.f, 0.f);
    size_t o = (size_t)b * NCHUNK * I2 + j;
    #pragma unroll
    for (int c = 0; c < NCHUNK; c++) {
        ((float2*)g_S)[o] = s;
        float2 P = ((float2*)g_P)[o];
        float2 q = ((float2*)g_q)[o];
        s.x = fmaf(P.x, s.x, q.x);
        s.y = fmaf(P.y, s.y, q.y);
        o += I2;
    }
}

__global__ __launch_bounds__(256) void scan_pass2()
{
    int b = blockIdx.z, c = blockIdx.y;
    int j = blockIdx.x * 256 + threadIdx.x;
    const int I2 = INNER / 2;
    float2 s = ((float2*)g_S)[((size_t)b * NCHUNK + c) * I2 + j];
    size_t idx = ((size_t)b * KK + (size_t)c * SCHUNK) * I2 + j;
    const __half2* lg2 = (const __half2*)g_lg;
    const __half2* u2  = (const __half2*)g_u;
    const __half2* z2  = (const __half2*)g_z;
    __half2* s2 = (__half2*)g_s;
    #pragma unroll 4
    for (int k = 0; k < SCHUNK; k++) {
        float2 lg = __half22float2(lg2[idx]);
        float2 u  = __half22float2(u2[idx]);
        float2 zz = __half22float2(z2[idx]);
        float la = 1.f / (1.f + expf(-lg.x));
        float lb = 1.f / (1.f + expf(-lg.y));
        s.x = fmaf(la, s.x, (1.f - la) * u.x);
        s.y = fmaf(lb, s.y, (1.f - lb) * u.y);
        s2[idx] = __floats2half2_rn(s.x * zz.x, s.y * zz.y);
        idx += I2;
    }
}

// ---------------- launch ------------------------------------------------------
extern "C" void kernel_launch(void* const* d_in, const int* in_sizes, int n_in,
                              void* d_out, int out_size)
{
    const float* x      = (const float*)d_in[0];
    const float* w_norm = (const float*)d_in[1];
    const float* W_in   = (const float*)d_in[2];
    const float* W_dt   = (const float*)d_in[3];
    const float* b_dt   = (const float*)d_in[4];
    const float* W_out  = (const float*)d_in[5];
    float* out = (float*)d_out;

    cudaFuncSetAttribute(gemm_tc<1>, cudaFuncAttributeMaxDynamicSharedMemorySize, GEMM_SMEM);
    cudaFuncSetAttribute(gemm_tc<2>, cudaFuncAttributeMaxDynamicSharedMemorySize, GEMM_SMEM);
    cudaFuncSetAttribute(gemm_tc<3>, cudaFuncAttributeMaxDynamicSharedMemorySize, GEMM_SMEM);

    convert_all<<<512, 256>>>(W_in, W_dt, W_out);
    rmsnorm_kernel<<<MROWS, 256>>>(x, w_norm);

    gemm_tc<1><<<dim3(2*INNER/128, MROWS/128), 256, GEMM_SMEM>>>(nullptr, nullptr);
    gemm_tc<2><<<dim3(INNER/128,   MROWS/128), 256, GEMM_SMEM>>>(b_dt, nullptr);

    scan_pass1 <<<dim3(INNER/512, NCHUNK, BB), 256>>>();
    scan_combine<<<dim3(INNER/512, BB),        256>>>();
    scan_pass2 <<<dim3(INNER/512, NCHUNK, BB), 256>>>();

    gemm_tc<3><<<dim3(DD/128,      MROWS/128), 256, GEMM_SMEM>>>(x, out);
}

// round 10
// speedup vs baseline: 5.7386x; 1.0027x over previous
#include <cuda_runtime.h>
#include <cuda_fp16.h>
#include <stdint.h>
#include <math.h>

#define BB 8
#define KK 2048
#define DD 1024
#define INNER 2048
#define MROWS (BB*KK)   // 16384
#define SCHUNK 128      // scan chunk length
#define NCHUNK (KK/SCHUNK)  // 16

// ---------------- device scratch (no allocs allowed) ------------------------
__device__ __half g_h  [(size_t)MROWS*DD];      // RMSNorm out fp16      32 MB
__device__ __half g_u  [(size_t)MROWS*INNER];   // silu(u) fp16          64 MB
__device__ __half g_z  [(size_t)MROWS*INNER];   // silu(z) fp16          64 MB
__device__ __half g_lg [(size_t)MROWS*INNER];   // dt logit fp16         64 MB
__device__ __half g_s  [(size_t)MROWS*INNER];   // scan*gate fp16        64 MB
__device__ __half g_wi [(size_t)2*INNER*DD];    // W_in fp16             16 MB
__device__ __half g_wd [(size_t)INNER*INNER];   // W_dt fp16              8 MB
__device__ __half g_wo [(size_t)DD*INNER];      // W_out fp16             4 MB
__device__ float  g_P  [(size_t)BB*NCHUNK*INNER];  // chunk decay prod    1 MB
__device__ float  g_q  [(size_t)BB*NCHUNK*INNER];  // chunk partial       1 MB
__device__ float  g_S  [(size_t)BB*NCHUNK*INNER];  // chunk start state   1 MB

// ---------------- PTX helpers ------------------------------------------------
__device__ __forceinline__ uint32_t smem_u32(const void* p) {
    uint32_t a;
    asm("{ .reg .u64 t; cvta.to.shared.u64 t, %1; cvt.u32.u64 %0, t; }"
        : "=r"(a) : "l"(p));
    return a;
}
__device__ __forceinline__ void cp_async16(uint32_t dst, const void* src) {
    asm volatile("cp.async.cg.shared.global [%0], [%1], 16;\n"
                 :: "r"(dst), "l"(src) : "memory");
}
__device__ __forceinline__ void cp_commit() {
    asm volatile("cp.async.commit_group;\n" ::: "memory");
}
template <int N>
__device__ __forceinline__ void cp_wait() {
    asm volatile("cp.async.wait_group %0;\n" :: "n"(N) : "memory");
}
__device__ __forceinline__ void ldsm4(uint32_t* r, uint32_t addr) {
    asm volatile("ldmatrix.sync.aligned.m8n8.x4.shared.b16 {%0,%1,%2,%3}, [%4];"
                 : "=r"(r[0]), "=r"(r[1]), "=r"(r[2]), "=r"(r[3]) : "r"(addr));
}
__device__ __forceinline__ void mma16816(float* c, const uint32_t* a,
                                         uint32_t b0, uint32_t b1) {
    asm volatile("mma.sync.aligned.m16n8k16.row.col.f32.f16.f16.f32 "
                 "{%0,%1,%2,%3}, {%4,%5,%6,%7}, {%8,%9}, {%0,%1,%2,%3};"
                 : "+f"(c[0]), "+f"(c[1]), "+f"(c[2]), "+f"(c[3])
                 : "r"(a[0]), "r"(a[1]), "r"(a[2]), "r"(a[3]), "r"(b0), "r"(b1));
}
__device__ __forceinline__ uint32_t pack_half2(float a, float b) {
    __half2 h = __halves2half2(__float2half_rn(a), __float2half_rn(b));
    return *(uint32_t*)&h;
}

// ---------------- fused weight conversion fp32 -> fp16 -----------------------
__global__ __launch_bounds__(256) void convert_all(
    const float* __restrict__ wi, const float* __restrict__ wd,
    const float* __restrict__ wo)
{
    const size_t n0 = (size_t)2*INNER*DD >> 2;
    const size_t n1 = (size_t)INNER*INNER >> 2;
    const size_t n2 = (size_t)DD*INNER   >> 2;
    size_t stride = (size_t)gridDim.x * blockDim.x;
    size_t t0 = (size_t)blockIdx.x * blockDim.x + threadIdx.x;
    for (size_t i = t0; i < n0; i += stride) {
        float4 v = ((const float4*)wi)[i];
        *(uint2*)(g_wi + 4*i) = make_uint2(pack_half2(v.x, v.y), pack_half2(v.z, v.w));
    }
    for (size_t i = t0; i < n1; i += stride) {
        float4 v = ((const float4*)wd)[i];
        *(uint2*)(g_wd + 4*i) = make_uint2(pack_half2(v.x, v.y), pack_half2(v.z, v.w));
    }
    for (size_t i = t0; i < n2; i += stride) {
        float4 v = ((const float4*)wo)[i];
        *(uint2*)(g_wo + 4*i) = make_uint2(pack_half2(v.x, v.y), pack_half2(v.z, v.w));
    }
}

// ---------------- RMSNorm -> fp16 --------------------------------------------
__global__ __launch_bounds__(256) void rmsnorm_kernel(
    const float* __restrict__ x, const float* __restrict__ w)
{
    int row = blockIdx.x;
    const float4* xr = (const float4*)(x + (size_t)row * DD);
    float4 v = xr[threadIdx.x];
    float ss = v.x*v.x + v.y*v.y + v.z*v.z + v.w*v.w;
    #pragma unroll
    for (int o = 16; o > 0; o >>= 1) ss += __shfl_xor_sync(0xffffffffu, ss, o);
    __shared__ float red[8];
    if ((threadIdx.x & 31) == 0) red[threadIdx.x >> 5] = ss;
    __syncthreads();
    float tot = red[0]+red[1]+red[2]+red[3]+red[4]+red[5]+red[6]+red[7];
    float inv = rsqrtf(tot * (1.0f / DD) + 1e-5f);
    float4 wv = ((const float4*)w)[threadIdx.x];
    size_t base = (size_t)row * DD + threadIdx.x * 4;
    *(uint2*)(g_h + base) = make_uint2(
        pack_half2(v.x*inv*wv.x, v.y*inv*wv.y),
        pack_half2(v.z*inv*wv.z, v.w*inv*wv.w));
}

// ---------------- mma.sync fp16 NT GEMM --------------------------------------
// C[M,N] = A[M,Kd]*B[N,Kd]^T, fp32 accumulate.
// MODE 1: A=g_h, B=g_wi : epi silu -> g_u (n<INNER) / g_z
// MODE 2: A=g_u, B=g_wd : epi (v + b_dt[n]) -> g_lg fp16 logit
// MODE 3: A=g_s, B=g_wo : epi x + v -> out
// BM=BN=128, BK=64; 8 warps 2(m)x4(n), warp tile 64x32; 3-stage cp.async.
// Inner loop software-pipelined: B frags double-buffered across k16,
// A frags loaded in mi-halves adjacent to their MMAs.
#define ROWB  144
#define TEN_B (128*ROWB)        // 18432 per tensor per stage
#define NSTG  3
#define STG_B (2*TEN_B)         // 36864
#define GEMM_SMEM (NSTG*STG_B)  // 110592 -> 2 CTAs/SM

template <int MODE>
__global__ __launch_bounds__(256, 2) void gemm_tc(
    const float* __restrict__ extra, float* __restrict__ outp)
{
    const __half *A, *B0;
    int Kd;
    if (MODE == 1)      { A = g_h; B0 = g_wi; Kd = DD;    }
    else if (MODE == 2) { A = g_u; B0 = g_wd; Kd = INNER; }
    else                { A = g_s; B0 = g_wo; Kd = INNER; }
    const int NT = Kd / 64;

    extern __shared__ __align__(128) char sm[];
    uint32_t sbase = smem_u32(sm);
    const int tid = threadIdx.x;
    const int l   = tid & 31;
    const int wid = tid >> 5;
    const int bm  = blockIdx.y * 128;
    const int bn  = blockIdx.x * 128;
    const int warp_m = (wid & 1) * 64;
    const int warp_n = (wid >> 1) * 32;

    const __half* srcA = A  + (size_t)bm * Kd;
    const __half* srcB = B0 + (size_t)bn * Kd;

    auto load_stage = [&](int stg, int kc) {
        uint32_t base = sbase + stg * STG_B;
        #pragma unroll
        for (int i = 0; i < 8; i++) {
            int c   = tid + i * 256;          // 0..2047
            int tns = c >> 10;                // 0: A, 1: B
            int idx = c & 1023;
            int row = idx >> 3;               // 0..127
            int seg = idx & 7;                // 0..7 (16B each)
            uint32_t dst = base + tns * TEN_B + row * ROWB + seg * 16;
            const __half* sp = tns ? srcB : srcA;
            cp_async16(dst, (const char*)(sp + (size_t)row * Kd + kc) + seg * 16);
        }
    };

    float acc[4][4][4];
    #pragma unroll
    for (int mi = 0; mi < 4; mi++)
        #pragma unroll
        for (int ni = 0; ni < 4; ni++)
            #pragma unroll
            for (int c = 0; c < 4; c++) acc[mi][ni][c] = 0.0f;

    const uint32_t a_off = (warp_m + (l & 15)) * ROWB + 16 * (l >> 4);
    const uint32_t b_off = (warp_n + (l & 15)) * ROWB + 16 * (l >> 4);

    load_stage(0, 0);  cp_commit();
    load_stage(1, 64); cp_commit();

    uint32_t bh[2][2][4];   // [buf][g][frag] — B frags double-buffered over k16

    for (int t = 0; t < NT; t++) {
        if (t + 1 < NT) cp_wait<1>();
        else            cp_wait<0>();
        __syncthreads();
        if (t + 2 < NT) { load_stage((t + 2) % 3, (t + 2) * 64); cp_commit(); }

        uint32_t sb = sbase + (t % 3) * STG_B;

        // preload B frags for k16 = 0
        #pragma unroll
        for (int g = 0; g < 2; g++)
            ldsm4(bh[0][g], sb + 1*TEN_B + b_off + g * (16*ROWB));

        #pragma unroll
        for (int k16 = 0; k16 < 4; k16++) {
            const int cur = k16 & 1, nxt = cur ^ 1;
            const uint32_t koff = k16 * 32;
            // prefetch next k16's B frags while current MMAs execute
            if (k16 < 3) {
                #pragma unroll
                for (int g = 0; g < 2; g++)
                    ldsm4(bh[nxt][g], sb + 1*TEN_B + b_off + g * (16*ROWB) + koff + 32);
            }
            #pragma unroll
            for (int mh = 0; mh < 2; mh++) {
                uint32_t ah[2][4];
                ldsm4(ah[0], sb + a_off + (mh*2+0) * (16*ROWB) + koff);
                ldsm4(ah[1], sb + a_off + (mh*2+1) * (16*ROWB) + koff);
                #pragma unroll
                for (int mi2 = 0; mi2 < 2; mi2++) {
                    const int mi = mh * 2 + mi2;
                    #pragma unroll
                    for (int ni = 0; ni < 4; ni++) {
                        const int g = ni >> 1, s = ni & 1;
                        mma16816(acc[mi][ni], ah[mi2],
                                 bh[cur][g][s], bh[cur][g][s + 2]);
                    }
                }
            }
        }
    }

    // ---------------- epilogue from registers --------------------------------
    #pragma unroll
    for (int mi = 0; mi < 4; mi++) {
        int m0 = bm + warp_m + mi * 16 + (l >> 2);
        #pragma unroll
        for (int ni = 0; ni < 4; ni++) {
            int n0 = bn + warp_n + ni * 8 + 2 * (l & 3);
            #pragma unroll
            for (int half = 0; half < 2; half++) {
                int m = m0 + half * 8;
                float v0 = acc[mi][ni][half * 2 + 0];
                float v1 = acc[mi][ni][half * 2 + 1];
                if (MODE == 1) {
                    float s0 = v0 / (1.f + expf(-v0));
                    float s1 = v1 / (1.f + expf(-v1));
                    if (bn < INNER)
                        *(uint32_t*)(g_u + (size_t)m * INNER + n0) = pack_half2(s0, s1);
                    else
                        *(uint32_t*)(g_z + (size_t)m * INNER + (n0 - INNER)) =
                            pack_half2(s0, s1);
                } else if (MODE == 2) {
                    float2 bv = *(const float2*)(extra + n0);
                    *(uint32_t*)(g_lg + (size_t)m * INNER + n0) =
                        pack_half2(v0 + bv.x, v1 + bv.y);
                } else {
                    size_t o = (size_t)m * DD + n0;
                    float2 xv = *(const float2*)(extra + o);
                    *(float2*)(outp + o) = make_float2(xv.x + v0, xv.y + v1);
                }
            }
        }
    }
}

// ---------------- chunked scan (half2-vectorized, 2 channels/thread) --------
__global__ __launch_bounds__(256) void scan_pass1()
{
    int b = blockIdx.z, c = blockIdx.y;
    int j = blockIdx.x * 256 + threadIdx.x;          // channel-pair 0..1023
    const int I2 = INNER / 2;
    size_t idx = ((size_t)b * KK + (size_t)c * SCHUNK) * I2 + j;
    const __half2* lg2 = (const __half2*)g_lg;
    const __half2* u2  = (const __half2*)g_u;
    float2 P = make_float2(1.f, 1.f), q = make_float2(0.f, 0.f);
    #pragma unroll 4
    for (int k = 0; k < SCHUNK; k++) {
        float2 lg = __half22float2(lg2[idx]);
        float2 u  = __half22float2(u2[idx]);
        float la = 1.f / (1.f + expf(-lg.x));
        float lb = 1.f / (1.f + expf(-lg.y));
        q.x = fmaf(la, q.x, (1.f - la) * u.x);
        q.y = fmaf(lb, q.y, (1.f - lb) * u.y);
        P.x *= la; P.y *= lb;
        idx += I2;
    }
    size_t o = ((size_t)b * NCHUNK + c) * I2 + j;
    ((float2*)g_P)[o] = P;
    ((float2*)g_q)[o] = q;
}

__global__ __launch_bounds__(256) void scan_combine()
{
    int b = blockIdx.y;
    int j = blockIdx.x * 256 + threadIdx.x;          // channel-pair 0..1023
    const int I2 = INNER / 2;
    float2 s = make_float2(0.f, 0.f);
    size_t o = (size_t)b * NCHUNK * I2 + j;
    #pragma unroll
    for (int c = 0; c < NCHUNK; c++) {
        ((float2*)g_S)[o] = s;
        float2 P = ((float2*)g_P)[o];
        float2 q = ((float2*)g_q)[o];
        s.x = fmaf(P.x, s.x, q.x);
        s.y = fmaf(P.y, s.y, q.y);
        o += I2;
    }
}

__global__ __launch_bounds__(256) void scan_pass2()
{
    int b = blockIdx.z, c = blockIdx.y;
    int j = blockIdx.x * 256 + threadIdx.x;
    const int I2 = INNER / 2;
    float2 s = ((float2*)g_S)[((size_t)b * NCHUNK + c) * I2 + j];
    size_t idx = ((size_t)b * KK + (size_t)c * SCHUNK) * I2 + j;
    const __half2* lg2 = (const __half2*)g_lg;
    const __half2* u2  = (const __half2*)g_u;
    const __half2* z2  = (const __half2*)g_z;
    __half2* s2 = (__half2*)g_s;
    #pragma unroll 4
    for (int k = 0; k < SCHUNK; k++) {
        float2 lg = __half22float2(lg2[idx]);
        float2 u  = __half22float2(u2[idx]);
        float2 zz = __half22float2(z2[idx]);
        float la = 1.f / (1.f + expf(-lg.x));
        float lb = 1.f / (1.f + expf(-lg.y));
        s.x = fmaf(la, s.x, (1.f - la) * u.x);
        s.y = fmaf(lb, s.y, (1.f - lb) * u.y);
        s2[idx] = __floats2half2_rn(s.x * zz.x, s.y * zz.y);
        idx += I2;
    }
}

// ---------------- launch ------------------------------------------------------
extern "C" void kernel_launch(void* const* d_in, const int* in_sizes, int n_in,
                              void* d_out, int out_size)
{
    const float* x      = (const float*)d_in[0];
    const float* w_norm = (const float*)d_in[1];
    const float* W_in   = (const float*)d_in[2];
    const float* W_dt   = (const float*)d_in[3];
    const float* b_dt   = (const float*)d_in[4];
    const float* W_out  = (const float*)d_in[5];
    float* out = (float*)d_out;

    cudaFuncSetAttribute(gemm_tc<1>, cudaFuncAttributeMaxDynamicSharedMemorySize, GEMM_SMEM);
    cudaFuncSetAttribute(gemm_tc<2>, cudaFuncAttributeMaxDynamicSharedMemorySize, GEMM_SMEM);
    cudaFuncSetAttribute(gemm_tc<3>, cudaFuncAttributeMaxDynamicSharedMemorySize, GEMM_SMEM);

    convert_all<<<512, 256>>>(W_in, W_dt, W_out);
    rmsnorm_kernel<<<MROWS, 256>>>(x, w_norm);

    gemm_tc<1><<<dim3(2*INNER/128, MROWS/128), 256, GEMM_SMEM>>>(nullptr, nullptr);
    gemm_tc<2><<<dim3(INNER/128,   MROWS/128), 256, GEMM_SMEM>>>(b_dt, nullptr);

    scan_pass1 <<<dim3(INNER/512, NCHUNK, BB), 256>>>();
    scan_combine<<<dim3(INNER/512, BB),        256>>>();
    scan_pass2 <<<dim3(INNER/512, NCHUNK, BB), 256>>>();

    gemm_tc<3><<<dim3(DD/128,      MROWS/128), 256, GEMM_SMEM>>>(x, out);
}